// round 7
// baseline (speedup 1.0000x reference)
#include <cuda_runtime.h>
#include <cuda_bf16.h>

#define BATCH      4096
#define INPUT_DIM  1024
#define BOND       32
#define OUT_DIM    512
#define NG1        128   // level-1 groups (8 cores each)
#define NG2        16    // level-2 groups (8 level-1 products each)

__device__ __align__(16) float g_buf1[NG1 * BOND * BOND];   // level-1 products
__device__ __align__(16) float g_buf2[NG2 * BOND * BOND];   // level-2 products
__device__ __align__(16) float g_w[OUT_DIM];                // (ones @ PIcores) @ proj
__device__ __align__(16) float g_P[BATCH];                  // per-row input products
__device__ int g_cnt1[NG2];   // finished level-1 blocks per level-2 group
__device__ int g_cnt2;        // finished level-2 foldings

// Row stride 36 floats: float4-aligned, conflict-free access patterns.
struct __align__(16) ChainSmem {
    float A[2][BOND][36];   // ping-pong running product / phase-3 G stage
    float B[BOND][36];      // staged next matrix (row-major)
};

template<bool LDCG>
__device__ __forceinline__ float4 ld4(const float* p) {
    if (LDCG) return __ldcg((const float4*)p);   // bypass L1 for cross-block data
    return *(const float4*)p;
}

// Product of GROUP consecutive row-major 32x32 matrices from src[base...].
// All GROUP matrices prefetched to registers first (MLP=GROUP).
// Thread (j=tid>>3, kt=(tid&7)*4) owns out[j][kt..kt+3].
template<int GROUP, bool LDCG>
__device__ __forceinline__ void chain_product_store(ChainSmem& s,
                                                    const float* __restrict__ src,
                                                    int base, float* __restrict__ dst) {
    const int tid = threadIdx.x;
    const int j  = tid >> 3;
    const int kt = (tid & 7) << 2;

    float4 m[GROUP];
#pragma unroll
    for (int t = 0; t < GROUP; ++t)
        m[t] = ld4<LDCG>(src + (size_t)(base + t) * (BOND * BOND) + tid * 4);

    *(float4*)&s.A[0][j][kt] = m[0];

    int cur = 0;
#pragma unroll
    for (int t = 1; t < GROUP; ++t) {
        __syncthreads();
        *(float4*)&s.B[j][kt] = m[t];
        __syncthreads();

        float a0 = 0.f, a1 = 0.f, a2 = 0.f, a3 = 0.f;
#pragma unroll
        for (int c4 = 0; c4 < 8; ++c4) {
            float4 av = *(const float4*)&s.A[cur][j][c4 * 4];
            float4 m0 = *(const float4*)&s.B[c4 * 4 + 0][kt];
            float4 m1 = *(const float4*)&s.B[c4 * 4 + 1][kt];
            float4 m2 = *(const float4*)&s.B[c4 * 4 + 2][kt];
            float4 m3 = *(const float4*)&s.B[c4 * 4 + 3][kt];
            a0 += av.x * m0.x + av.y * m1.x + av.z * m2.x + av.w * m3.x;
            a1 += av.x * m0.y + av.y * m1.y + av.z * m2.y + av.w * m3.y;
            a2 += av.x * m0.z + av.y * m1.z + av.z * m2.z + av.w * m3.z;
            a3 += av.x * m0.w + av.y * m1.w + av.z * m2.w + av.w * m3.w;
        }
        *(float4*)&s.A[cur ^ 1][j][kt] = make_float4(a0, a1, a2, a3);
        cur ^= 1;
    }
    __syncthreads();
    *(float4*)(dst + tid * 4) = *(float4*)&s.A[cur][j][kt];
}

// One fused kernel: blocks 0..127 run the chain tree (with atomic-counter
// continuation through levels 2 and 3); blocks 128..639 compute per-row input
// products (overlapping the 16.8MB read with the tree's serial latency).
__global__ void __launch_bounds__(256)
k_main(const float* __restrict__ cores, const float* __restrict__ proj,
       const float* __restrict__ inputs) {
    const int bid = blockIdx.x;
    const int tid = threadIdx.x;

    if (bid >= NG1) {
        // ---- input-product blocks: warp per row, no barriers ----
        const int warp = tid >> 5, lane = tid & 31;
        const long b = (long)(bid - NG1) * 8 + warp;
        const float* row = inputs + b * INPUT_DIM;
        float4 v[8];
#pragma unroll
        for (int i = 0; i < 8; ++i)
            v[i] = *(const float4*)(row + (lane + 32 * i) * 4);
        float p = 1.f;
#pragma unroll
        for (int i = 0; i < 8; ++i)
            p *= (v[i].x * v[i].y) * (v[i].z * v[i].w);
#pragma unroll
        for (int off = 16; off; off >>= 1)
            p *= __shfl_xor_sync(0xffffffffu, p, off);
        if (lane == 0) g_P[b] = p;
        return;
    }

    // ---- tree blocks ----
    __shared__ ChainSmem s;
    __shared__ int s_last;
    const int j  = tid >> 3;
    const int kt = (tid & 7) << 2;

    // Level 1: product of 8 cores -> g_buf1[bid]
    chain_product_store<8, false>(s, cores, bid * 8, g_buf1 + bid * (BOND * BOND));
    __threadfence();                               // release g_buf1 writes
    if (tid == 0) s_last = (atomicAdd(&g_cnt1[bid >> 3], 1) == 7);
    __syncthreads();
    if (!s_last) return;
    __threadfence();                               // acquire peers' g_buf1 writes

    // Level 2 (16 surviving blocks): fold 8 level-1 products -> g_buf2[grp]
    const int grp = bid >> 3;
    chain_product_store<8, true>(s, g_buf1, grp * 8, g_buf2 + grp * (BOND * BOND));
    __threadfence();
    if (tid == 0) s_last = (atomicAdd(&g_cnt2, 1) == NG2 - 1);
    __syncthreads();
    if (!s_last) return;
    __threadfence();

    // Level 3 (1 block): vector chain u = ones @ G0 @ ... @ G15.
    // All 8 warps stage G matrices into smem ping-pong; warp 0 computes.
    {
        float4 v0 = ld4<true>(g_buf2 + tid * 4);   // stage matrix 0 -> A[0]
        *(float4*)&s.A[0][j][kt] = v0;
    }
    __syncthreads();

    float v = 1.0f;                                // warp 0: u[lane]
#pragma unroll
    for (int t = 0; t < NG2; ++t) {
        float4 nx;
        if (t < NG2 - 1)
            nx = ld4<true>(g_buf2 + (size_t)(t + 1) * (BOND * BOND) + tid * 4);
        if ((tid >> 5) == 0) {
            const float (*G)[36] = s.A[t & 1];
            float acc0 = 0.f, acc1 = 0.f;
#pragma unroll
            for (int jj = 0; jj < BOND; jj += 2) {
                acc0 += __shfl_sync(0xffffffffu, v, jj)     * G[jj][tid];
                acc1 += __shfl_sync(0xffffffffu, v, jj + 1) * G[jj + 1][tid];
            }
            v = acc0 + acc1;
        }
        if (t < NG2 - 1)
            *(float4*)&s.A[(t + 1) & 1][j][kt] = nx;   // disjoint from A[t&1]
        __syncthreads();
    }

    __shared__ float u_s[BOND];
    if ((tid >> 5) == 0) u_s[tid] = v;
    __syncthreads();

    // w = u @ projection  (2 outputs per thread, coalesced proj reads)
    for (int o = tid; o < OUT_DIM; o += 256) {
        float acc = 0.f;
#pragma unroll
        for (int k = 0; k < BOND; ++k) acc += u_s[k] * proj[k * OUT_DIM + o];
        g_w[o] = acc;
    }

    // Reset continuation counters for the next graph replay (all atomics
    // are complete by construction once this block runs).
    if (tid < NG2) g_cnt1[tid] = 0;
    if (tid == 0)  g_cnt2 = 0;
}

// Pure-write kernel: out[b,:] = P[b] * w + bias. Warp per row, no barriers.
__global__ void __launch_bounds__(256)
k_write(const float* __restrict__ bias, float* __restrict__ out) {
    const int warp = threadIdx.x >> 5;
    const int lane = threadIdx.x & 31;
    const long b   = (long)blockIdx.x * 8 + warp;

    const float p = g_P[b];
    float* orow = out + b * OUT_DIM;
#pragma unroll
    for (int i = 0; i < 4; ++i) {
        const int o4 = (lane + 32 * i) * 4;
        float4 wv = *(const float4*)(g_w + o4);
        float4 bv = *(const float4*)(bias + o4);
        float4 r;
        r.x = fmaf(p, wv.x, bv.x);
        r.y = fmaf(p, wv.y, bv.y);
        r.z = fmaf(p, wv.z, bv.z);
        r.w = fmaf(p, wv.w, bv.w);
        *(float4*)(orow + o4) = r;
    }
}

extern "C" void kernel_launch(void* const* d_in, const int* in_sizes, int n_in,
                              void* d_out, int out_size) {
    const float* inputs = (const float*)d_in[0];   // [4096, 1024]
    const float* cores  = (const float*)d_in[1];   // [1024, 32, 32]
    const float* proj   = (const float*)d_in[2];   // [32, 512]
    const float* bias   = (const float*)d_in[3];   // [512]
    float*       out    = (float*)d_out;           // [4096, 512]

    (void)in_sizes; (void)n_in; (void)out_size;

    k_main <<<NG1 + BATCH / 8, 256>>>(cores, proj, inputs);
    k_write<<<BATCH / 8, 256>>>(bias, out);
}

// round 9
// speedup vs baseline: 1.2432x; 1.2432x over previous
#include <cuda_runtime.h>
#include <cuda_bf16.h>

#define BATCH      4096
#define INPUT_DIM  1024
#define BOND       32
#define OUT_DIM    512
#define NG1        128   // level-1 groups (8 cores each)
#define NG2        16    // level-2 groups (8 level-1 products each)

__device__ __align__(16) float g_buf1[NG1 * BOND * BOND];
__device__ __align__(16) float g_buf2[NG2 * BOND * BOND];
__device__ __align__(16) float g_w[OUT_DIM];
__device__ int g_cnt2;   // continuation counter inside k_chain2fin

// Row stride 36 floats: float4-aligned, conflict-free patterns.
struct __align__(16) ChainSmem {
    float A[2][BOND][36];   // ping-pong running product / finalize G stage
    float B[BOND][36];      // staged next matrix (row-major)
};

// Product of GROUP consecutive row-major 32x32 matrices from src[base...].
// All GROUP matrices prefetched to registers first (MLP=GROUP).
// Thread (j=tid>>3, kt=(tid&7)*4) owns out[j][kt..kt+3].
template<int GROUP>
__device__ __forceinline__ void chain_product_store(ChainSmem& s,
                                                    const float* __restrict__ src,
                                                    int base, float* __restrict__ dst) {
    const int tid = threadIdx.x;
    const int j  = tid >> 3;
    const int kt = (tid & 7) << 2;

    float4 m[GROUP];
#pragma unroll
    for (int t = 0; t < GROUP; ++t)
        m[t] = *(const float4*)(src + (size_t)(base + t) * (BOND * BOND) + tid * 4);

    *(float4*)&s.A[0][j][kt] = m[0];

    int cur = 0;
#pragma unroll
    for (int t = 1; t < GROUP; ++t) {
        __syncthreads();
        *(float4*)&s.B[j][kt] = m[t];
        __syncthreads();

        float a0 = 0.f, a1 = 0.f, a2 = 0.f, a3 = 0.f;
#pragma unroll
        for (int c4 = 0; c4 < 8; ++c4) {
            float4 av = *(const float4*)&s.A[cur][j][c4 * 4];
            float4 m0 = *(const float4*)&s.B[c4 * 4 + 0][kt];
            float4 m1 = *(const float4*)&s.B[c4 * 4 + 1][kt];
            float4 m2 = *(const float4*)&s.B[c4 * 4 + 2][kt];
            float4 m3 = *(const float4*)&s.B[c4 * 4 + 3][kt];
            a0 += av.x * m0.x + av.y * m1.x + av.z * m2.x + av.w * m3.x;
            a1 += av.x * m0.y + av.y * m1.y + av.z * m2.y + av.w * m3.y;
            a2 += av.x * m0.z + av.y * m1.z + av.z * m2.z + av.w * m3.z;
            a3 += av.x * m0.w + av.y * m1.w + av.z * m2.w + av.w * m3.w;
        }
        *(float4*)&s.A[cur ^ 1][j][kt] = make_float4(a0, a1, a2, a3);
        cur ^= 1;
    }
    __syncthreads();
    *(float4*)(dst + tid * 4) = *(float4*)&s.A[cur][j][kt];
}

// Level 1: 128 blocks, product of 8 cores each -> g_buf1
__global__ void __launch_bounds__(256) k_chain1(const float* __restrict__ cores) {
    __shared__ ChainSmem s;
    chain_product_store<8>(s, cores, blockIdx.x * 8, g_buf1 + blockIdx.x * (BOND * BOND));
}

// Level 2 + finalize in one kernel: 16 blocks fold 8 level-1 products each;
// the last finisher (counter continuation) runs the vector chain + projection.
__global__ void __launch_bounds__(256) k_chain2fin(const float* __restrict__ proj) {
    __shared__ ChainSmem s;
    __shared__ int s_last;
    const int tid = threadIdx.x;
    const int j  = tid >> 3;
    const int kt = (tid & 7) << 2;

    chain_product_store<8>(s, g_buf1, blockIdx.x * 8, g_buf2 + blockIdx.x * (BOND * BOND));
    __threadfence();                                   // release g_buf2
    if (tid == 0) s_last = (atomicAdd(&g_cnt2, 1) == NG2 - 1);
    __syncthreads();
    if (!s_last) return;
    __threadfence();                                   // acquire peers' g_buf2

    // Vector chain u = ones @ G0 @ ... @ G15; all 8 warps stage G into
    // the smem ping-pong, warp 0 computes via shuffle broadcast.
    *(float4*)&s.A[0][j][kt] = __ldcg((const float4*)(g_buf2 + tid * 4));
    __syncthreads();

    float v = 1.0f;
#pragma unroll
    for (int t = 0; t < NG2; ++t) {
        float4 nx;
        if (t < NG2 - 1)
            nx = __ldcg((const float4*)(g_buf2 + (size_t)(t + 1) * (BOND * BOND) + tid * 4));
        if ((tid >> 5) == 0) {
            const float (*G)[36] = s.A[t & 1];
            float acc0 = 0.f, acc1 = 0.f;
#pragma unroll
            for (int jj = 0; jj < BOND; jj += 2) {
                acc0 += __shfl_sync(0xffffffffu, v, jj)     * G[jj][tid];
                acc1 += __shfl_sync(0xffffffffu, v, jj + 1) * G[jj + 1][tid];
            }
            v = acc0 + acc1;
        }
        if (t < NG2 - 1)
            *(float4*)&s.A[(t + 1) & 1][j][kt] = nx;   // disjoint buffer
        __syncthreads();
    }

    __shared__ float u_s[BOND];
    if ((tid >> 5) == 0) u_s[tid] = v;
    __syncthreads();

    for (int o = tid; o < OUT_DIM; o += 256) {
        float acc = 0.f;
#pragma unroll
        for (int k = 0; k < BOND; ++k) acc += u_s[k] * proj[k * OUT_DIM + o];
        g_w[o] = acc;
    }

    if (tid == 0) g_cnt2 = 0;                          // reset for next graph replay
}

// Output: 2 warps per row (occ ~84%). Each warp reduces half the row's
// product, pair combines via smem, each warp writes half the outputs.
__global__ void __launch_bounds__(256) k_output(const float* __restrict__ x,
                                                const float* __restrict__ bias,
                                                float* __restrict__ out) {
    const int warp = threadIdx.x >> 5;        // 0..7
    const int lane = threadIdx.x & 31;
    const int rb   = warp >> 1;               // row within block: 0..3
    const int half = warp & 1;                // which half of the row
    const long b   = (long)blockIdx.x * 4 + rb;

    const float* src = x + b * INPUT_DIM + half * (INPUT_DIM / 2);
    float4 v[4];
#pragma unroll
    for (int i = 0; i < 4; ++i)               // 4 front-batched LDG.128, coalesced
        v[i] = *(const float4*)(src + (lane + 32 * i) * 4);

    float p = 1.f;
#pragma unroll
    for (int i = 0; i < 4; ++i)
        p *= (v[i].x * v[i].y) * (v[i].z * v[i].w);
#pragma unroll
    for (int off = 16; off; off >>= 1)
        p *= __shfl_xor_sync(0xffffffffu, p, off);

    __shared__ float part[4][2];
    if (lane == 0) part[rb][half] = p;
    __syncthreads();
    const float P = part[rb][0] * part[rb][1];

    // This warp writes its half of the 512 outputs (256 floats, coalesced).
    float* orow = out + b * OUT_DIM + half * (OUT_DIM / 2);
    const float* wv2 = g_w  + half * (OUT_DIM / 2);
    const float* bv2 = bias + half * (OUT_DIM / 2);
#pragma unroll
    for (int i = 0; i < 2; ++i) {
        const int o4 = (lane + 32 * i) * 4;
        float4 wv = *(const float4*)(wv2 + o4);
        float4 bv = *(const float4*)(bv2 + o4);
        float4 r;
        r.x = fmaf(P, wv.x, bv.x);
        r.y = fmaf(P, wv.y, bv.y);
        r.z = fmaf(P, wv.z, bv.z);
        r.w = fmaf(P, wv.w, bv.w);
        *(float4*)(orow + o4) = r;
    }
}

extern "C" void kernel_launch(void* const* d_in, const int* in_sizes, int n_in,
                              void* d_out, int out_size) {
    const float* inputs = (const float*)d_in[0];   // [4096, 1024]
    const float* cores  = (const float*)d_in[1];   // [1024, 32, 32]
    const float* proj   = (const float*)d_in[2];   // [32, 512]
    const float* bias   = (const float*)d_in[3];   // [512]
    float*       out    = (float*)d_out;           // [4096, 512]

    (void)in_sizes; (void)n_in; (void)out_size;

    k_chain1   <<<NG1, 256>>>(cores);
    k_chain2fin<<<NG2, 256>>>(proj);
    k_output   <<<BATCH / 4, 256>>>(inputs, bias, out);
}

// round 17
// speedup vs baseline: 1.2857x; 1.0342x over previous
#include <cuda_runtime.h>
#include <cuda_bf16.h>

#define BATCH      4096
#define INPUT_DIM  1024
#define BOND       32
#define OUT_DIM    512
#define NG1        128   // level-1 groups (8 cores each)
#define NG2        16    // level-2 groups (8 level-1 products each)

__device__ __align__(16) float g_buf1[NG1 * BOND * BOND];
__device__ __align__(16) float g_buf2[NG2 * BOND * BOND];
__device__ __align__(16) float g_w[OUT_DIM];
__device__ int g_cnt1[NG2];
__device__ int g_cnt2;

// Row stride 36 floats: float4-aligned, conflict-free patterns.
struct __align__(16) ChainSmem {
    float A[2][BOND][36];   // ping-pong running product / finalize G stage
    float B[BOND][36];      // staged next matrix (row-major)
};

template<bool LDCG>
__device__ __forceinline__ float4 ld4(const float* p) {
    if (LDCG) return __ldcg((const float4*)p);
    return *(const float4*)p;
}

// Product of 8 consecutive row-major 32x32 matrices from src[base...].
// ROLLING prefetch: exactly one next-matrix float4 (4 regs) in flight,
// issued before the matmul that hides it. No register-array spills.
// Thread (j=tid>>3, kt=(tid&7)*4) owns out[j][kt..kt+3].
template<bool LDCG>
__device__ __forceinline__ void chain8(ChainSmem& s, const float* __restrict__ src,
                                       int base, float* __restrict__ dst) {
    const int tid = threadIdx.x;
    const int j  = tid >> 3;
    const int kt = (tid & 7) << 2;
    const float* p = src + (size_t)base * (BOND * BOND) + tid * 4;

    float4 cur = ld4<LDCG>(p);                       // matrix 0
    float4 nxt = ld4<LDCG>(p + BOND * BOND);         // matrix 1 in flight
    *(float4*)&s.A[0][j][kt] = cur;

    int pp = 0;
#pragma unroll
    for (int t = 1; t < 8; ++t) {
        cur = nxt;
        if (t < 7)                                   // issue next LDG early;
            nxt = ld4<LDCG>(p + (size_t)(t + 1) * (BOND * BOND));  // hidden by matmul
        __syncthreads();                             // prior iter done with s.B
        *(float4*)&s.B[j][kt] = cur;
        __syncthreads();                             // s.B ready

        float a0 = 0.f, a1 = 0.f, a2 = 0.f, a3 = 0.f;
#pragma unroll
        for (int c4 = 0; c4 < 8; ++c4) {
            float4 av = *(const float4*)&s.A[pp][j][c4 * 4];
            float4 m0 = *(const float4*)&s.B[c4 * 4 + 0][kt];
            float4 m1 = *(const float4*)&s.B[c4 * 4 + 1][kt];
            float4 m2 = *(const float4*)&s.B[c4 * 4 + 2][kt];
            float4 m3 = *(const float4*)&s.B[c4 * 4 + 3][kt];
            a0 += av.x * m0.x + av.y * m1.x + av.z * m2.x + av.w * m3.x;
            a1 += av.x * m0.y + av.y * m1.y + av.z * m2.y + av.w * m3.y;
            a2 += av.x * m0.z + av.y * m1.z + av.z * m2.z + av.w * m3.z;
            a3 += av.x * m0.w + av.y * m1.w + av.z * m2.w + av.w * m3.w;
        }
        *(float4*)&s.A[pp ^ 1][j][kt] = make_float4(a0, a1, a2, a3);
        pp ^= 1;
    }
    __syncthreads();
    *(float4*)(dst + tid * 4) = *(float4*)&s.A[pp][j][kt];
}

// Whole tree in ONE kernel: 128 blocks do level 1; per-group-of-8 last
// finisher continues to level 2; the 16th level-2 finisher runs the vector
// chain + projection. No spinning; counters reset for graph replay.
__global__ void __launch_bounds__(256)
k_tree(const float* __restrict__ cores, const float* __restrict__ proj) {
    __shared__ ChainSmem s;
    __shared__ int s_last;
    const int bid = blockIdx.x;
    const int tid = threadIdx.x;
    const int j  = tid >> 3;
    const int kt = (tid & 7) << 2;

    // ---- Level 1 ----
    chain8<false>(s, cores, bid * 8, g_buf1 + bid * (BOND * BOND));
    __threadfence();                                       // release g_buf1
    if (tid == 0) s_last = (atomicAdd(&g_cnt1[bid >> 3], 1) == 7);
    __syncthreads();
    if (!s_last) return;
    if (tid == 0) g_cnt1[bid >> 3] = 0;                    // reset for next replay
    __threadfence();                                       // acquire peers' g_buf1

    // ---- Level 2 (16 surviving blocks) ----
    const int grp = bid >> 3;
    chain8<true>(s, g_buf1, grp * 8, g_buf2 + grp * (BOND * BOND));
    __threadfence();                                       // release g_buf2
    if (tid == 0) s_last = (atomicAdd(&g_cnt2, 1) == NG2 - 1);
    __syncthreads();
    if (!s_last) return;
    if (tid == 0) g_cnt2 = 0;                              // reset for next replay
    __threadfence();                                       // acquire peers' g_buf2

    // ---- Level 3 (1 block): u = ones @ G0 @ ... @ G15, then w = u @ proj ----
    *(float4*)&s.A[0][j][kt] = __ldcg((const float4*)(g_buf2 + tid * 4));
    __syncthreads();

    float v = 1.0f;
#pragma unroll
    for (int t = 0; t < NG2; ++t) {
        float4 nx;
        if (t < NG2 - 1)
            nx = __ldcg((const float4*)(g_buf2 + (size_t)(t + 1) * (BOND * BOND) + tid * 4));
        if ((tid >> 5) == 0) {
            const float (*G)[36] = s.A[t & 1];
            float acc0 = 0.f, acc1 = 0.f;
#pragma unroll
            for (int jj = 0; jj < BOND; jj += 2) {
                acc0 += __shfl_sync(0xffffffffu, v, jj)     * G[jj][tid];
                acc1 += __shfl_sync(0xffffffffu, v, jj + 1) * G[jj + 1][tid];
            }
            v = acc0 + acc1;
        }
        if (t < NG2 - 1)
            *(float4*)&s.A[(t + 1) & 1][j][kt] = nx;       // disjoint buffer
        __syncthreads();
    }

    __shared__ float u_s[BOND];
    if ((tid >> 5) == 0) u_s[tid] = v;
    __syncthreads();

    for (int o = tid; o < OUT_DIM; o += 256) {
        float acc = 0.f;
#pragma unroll
        for (int k = 0; k < BOND; ++k) acc += u_s[k] * proj[k * OUT_DIM + o];
        g_w[o] = acc;
    }
}

// Output: 2 warps per row (occ ~86%). Each warp reduces half the row's
// product, pair combines via smem, each warp writes half the outputs.
__global__ void __launch_bounds__(256) k_output(const float* __restrict__ x,
                                                const float* __restrict__ bias,
                                                float* __restrict__ out) {
    const int warp = threadIdx.x >> 5;        // 0..7
    const int lane = threadIdx.x & 31;
    const int rb   = warp >> 1;               // row within block: 0..3
    const int half = warp & 1;                // which half of the row
    const long b   = (long)blockIdx.x * 4 + rb;

    const float* src = x + b * INPUT_DIM + half * (INPUT_DIM / 2);
    float4 v[4];
#pragma unroll
    for (int i = 0; i < 4; ++i)               // 4 front-batched LDG.128, coalesced
        v[i] = *(const float4*)(src + (lane + 32 * i) * 4);

    float p = 1.f;
#pragma unroll
    for (int i = 0; i < 4; ++i)
        p *= (v[i].x * v[i].y) * (v[i].z * v[i].w);
#pragma unroll
    for (int off = 16; off; off >>= 1)
        p *= __shfl_xor_sync(0xffffffffu, p, off);

    __shared__ float part[4][2];
    if (lane == 0) part[rb][half] = p;
    __syncthreads();
    const float P = part[rb][0] * part[rb][1];

    float* orow = out + b * OUT_DIM + half * (OUT_DIM / 2);
    const float* wv2 = g_w  + half * (OUT_DIM / 2);
    const float* bv2 = bias + half * (OUT_DIM / 2);
#pragma unroll
    for (int i = 0; i < 2; ++i) {
        const int o4 = (lane + 32 * i) * 4;
        float4 wv = *(const float4*)(wv2 + o4);
        float4 bv = *(const float4*)(bv2 + o4);
        float4 r;
        r.x = fmaf(P, wv.x, bv.x);
        r.y = fmaf(P, wv.y, bv.y);
        r.z = fmaf(P, wv.z, bv.z);
        r.w = fmaf(P, wv.w, bv.w);
        *(float4*)(orow + o4) = r;
    }
}

extern "C" void kernel_launch(void* const* d_in, const int* in_sizes, int n_in,
                              void* d_out, int out_size) {
    const float* inputs = (const float*)d_in[0];   // [4096, 1024]
    const float* cores  = (const float*)d_in[1];   // [1024, 32, 32]
    const float* proj   = (const float*)d_in[2];   // [32, 512]
    const float* bias   = (const float*)d_in[3];   // [512]
    float*       out    = (float*)d_out;           // [4096, 512]

    (void)in_sizes; (void)n_in; (void)out_size;

    k_tree  <<<NG1, 256>>>(cores, proj);
    k_output<<<BATCH / 4, 256>>>(inputs, bias, out);
}